// round 2
// baseline (speedup 1.0000x reference)
#include <cuda_runtime.h>
#include <cuda_bf16.h>
#include <math.h>

// Problem constants
#define BATCH   8
#define SEQ     512
#define DMODEL  512
#define NHEAD   8
#define DHEAD   64
#define DFF     2048
#define NLAYER  6
#define DIN     64
#define MTOK    (BATCH * SEQ)          // 4096 token rows

// ---------------- scratch (static device globals; no allocation) ------------
__device__ float g_pe [SEQ * DMODEL];            // 1 MB
__device__ float g_x  [MTOK * DMODEL];           // 8 MB
__device__ float g_q  [MTOK * DMODEL];
__device__ float g_k  [MTOK * DMODEL];
__device__ float g_v  [MTOK * DMODEL];
__device__ float g_ctx[MTOK * DMODEL];
__device__ float g_tmp[MTOK * DMODEL];
__device__ float g_ffh[MTOK * DFF];              // 32 MB
__device__ float g_sc [BATCH * NHEAD * SEQ * SEQ]; // 64 MB

// ---------------- positional encoding table ---------------------------------
__global__ void pe_kernel(float* __restrict__ pe) {
    int s = blockIdx.x;          // 0..511
    int i = threadIdx.x;         // 0..255 (pairs)
    float div = expf(-(float)(2 * i) * (logf(10000.0f) / (float)DMODEL));
    float ang = (float)s * div;
    pe[s * DMODEL + 2 * i]     = sinf(ang);
    pe[s * DMODEL + 2 * i + 1] = cosf(ang);
}

// ---------------- generic GEMM: C[M,N] = A[M,K] @ B[K,N] + bias, epilogue ---
// Tile 128x64x16, 256 threads, 8x4 per thread. Requires M%128==0, N%64==0, K%16==0.
#define EPI_NONE 0
#define EPI_RELU 1
#define EPI_PE   2

__global__ __launch_bounds__(256)
void gemm_kernel(const float* __restrict__ A, const float* __restrict__ B,
                 const float* __restrict__ bias, float* __restrict__ C,
                 int M, int N, int K, int epi, float alpha,
                 const float* __restrict__ pe) {
    __shared__ float As[16][128];
    __shared__ float Bs[16][64];

    int tid = threadIdx.x;
    int tx = tid & 15, ty = tid >> 4;
    int row0 = blockIdx.y * 128;
    int col0 = blockIdx.x * 64;

    float acc[8][4];
#pragma unroll
    for (int i = 0; i < 8; i++)
#pragma unroll
        for (int j = 0; j < 4; j++) acc[i][j] = 0.0f;

    for (int k0 = 0; k0 < K; k0 += 16) {
        // A tile: 128x16 = 512 float4 loads, 2 per thread, store transposed
#pragma unroll
        for (int li = 0; li < 2; li++) {
            int idx = tid + li * 256;
            int r  = idx >> 2;
            int c4 = (idx & 3) * 4;
            float4 v = *(const float4*)&A[(size_t)(row0 + r) * K + k0 + c4];
            As[c4 + 0][r] = v.x; As[c4 + 1][r] = v.y;
            As[c4 + 2][r] = v.z; As[c4 + 3][r] = v.w;
        }
        // B tile: 16x64 = 256 float4 loads, 1 per thread
        {
            int r  = tid >> 4;
            int c4 = (tid & 15) * 4;
            *(float4*)&Bs[r][c4] = *(const float4*)&B[(size_t)(k0 + r) * N + col0 + c4];
        }
        __syncthreads();
#pragma unroll
        for (int k = 0; k < 16; k++) {
            float a[8], bb[4];
#pragma unroll
            for (int i = 0; i < 8; i++) a[i] = As[k][ty * 8 + i];
#pragma unroll
            for (int j = 0; j < 4; j++) bb[j] = Bs[k][tx * 4 + j];
#pragma unroll
            for (int i = 0; i < 8; i++)
#pragma unroll
                for (int j = 0; j < 4; j++) acc[i][j] += a[i] * bb[j];
        }
        __syncthreads();
    }

    int c = col0 + tx * 4;
    float4 bv = *(const float4*)&bias[c];
#pragma unroll
    for (int i = 0; i < 8; i++) {
        int r = row0 + ty * 8 + i;
        float4 o;
        o.x = acc[i][0] + bv.x; o.y = acc[i][1] + bv.y;
        o.z = acc[i][2] + bv.z; o.w = acc[i][3] + bv.w;
        if (epi == EPI_RELU) {
            o.x = fmaxf(o.x, 0.f); o.y = fmaxf(o.y, 0.f);
            o.z = fmaxf(o.z, 0.f); o.w = fmaxf(o.w, 0.f);
        } else if (epi == EPI_PE) {
            const float* per = pe + (size_t)(r & (SEQ - 1)) * DMODEL + c;
            float4 pv = *(const float4*)per;
            o.x = o.x * alpha + pv.x; o.y = o.y * alpha + pv.y;
            o.z = o.z * alpha + pv.z; o.w = o.w * alpha + pv.w;
        }
        *(float4*)&C[(size_t)r * N + c] = o;
    }
}

// ---------------- QK^T: E[bh,i,j] = scale * sum_d Q[b,i,h*64+d]*K[b,j,h*64+d]
// Tile 128x128, K=64, 256 threads, 8x8 per thread. grid (4,4,64)
__global__ __launch_bounds__(256)
void qk_kernel(const float* __restrict__ Q, const float* __restrict__ Km,
               float* __restrict__ E, float scale) {
    __shared__ float As[16][128];
    __shared__ float Bs[16][128];

    int tid = threadIdx.x;
    int tx = tid & 15, ty = tid >> 4;
    int z = blockIdx.z;
    int b = z >> 3, h = z & 7;
    const float* qb = Q  + (size_t)b * SEQ * DMODEL + h * DHEAD;
    const float* kb = Km + (size_t)b * SEQ * DMODEL + h * DHEAD;
    float* eb = E + (size_t)z * SEQ * SEQ;
    int row0 = blockIdx.y * 128;
    int col0 = blockIdx.x * 128;

    float acc[8][8];
#pragma unroll
    for (int i = 0; i < 8; i++)
#pragma unroll
        for (int j = 0; j < 8; j++) acc[i][j] = 0.0f;

    for (int k0 = 0; k0 < DHEAD; k0 += 16) {
#pragma unroll
        for (int li = 0; li < 2; li++) {
            int idx = tid + li * 256;
            int r  = idx >> 2;
            int c4 = (idx & 3) * 4;
            float4 va = *(const float4*)&qb[(size_t)(row0 + r) * DMODEL + k0 + c4];
            As[c4 + 0][r] = va.x; As[c4 + 1][r] = va.y;
            As[c4 + 2][r] = va.z; As[c4 + 3][r] = va.w;
            float4 vb = *(const float4*)&kb[(size_t)(col0 + r) * DMODEL + k0 + c4];
            Bs[c4 + 0][r] = vb.x; Bs[c4 + 1][r] = vb.y;
            Bs[c4 + 2][r] = vb.z; Bs[c4 + 3][r] = vb.w;
        }
        __syncthreads();
#pragma unroll
        for (int k = 0; k < 16; k++) {
            float a[8], bb[8];
#pragma unroll
            for (int i = 0; i < 8; i++) a[i]  = As[k][ty * 8 + i];
#pragma unroll
            for (int j = 0; j < 8; j++) bb[j] = Bs[k][tx * 8 + j];
#pragma unroll
            for (int i = 0; i < 8; i++)
#pragma unroll
                for (int j = 0; j < 8; j++) acc[i][j] += a[i] * bb[j];
        }
        __syncthreads();
    }

#pragma unroll
    for (int i = 0; i < 8; i++) {
        int r = row0 + ty * 8 + i;
#pragma unroll
        for (int j4 = 0; j4 < 2; j4++) {
            float4 o;
            o.x = acc[i][j4 * 4 + 0] * scale;
            o.y = acc[i][j4 * 4 + 1] * scale;
            o.z = acc[i][j4 * 4 + 2] * scale;
            o.w = acc[i][j4 * 4 + 3] * scale;
            *(float4*)&eb[(size_t)r * SEQ + col0 + tx * 8 + j4 * 4] = o;
        }
    }
}

// ---------------- softmax over last dim (512), one block per row ------------
__global__ __launch_bounds__(128)
void softmax_kernel(float* __restrict__ sc) {
    __shared__ float red[128];
    int row = blockIdx.x;
    float4* p = (float4*)(sc + (size_t)row * SEQ);
    float4 v = p[threadIdx.x];
    float m = fmaxf(fmaxf(v.x, v.y), fmaxf(v.z, v.w));
    red[threadIdx.x] = m;
    __syncthreads();
    for (int s = 64; s > 0; s >>= 1) {
        if (threadIdx.x < s) red[threadIdx.x] = fmaxf(red[threadIdx.x], red[threadIdx.x + s]);
        __syncthreads();
    }
    m = red[0];
    __syncthreads();
    v.x = __expf(v.x - m); v.y = __expf(v.y - m);
    v.z = __expf(v.z - m); v.w = __expf(v.w - m);
    red[threadIdx.x] = v.x + v.y + v.z + v.w;
    __syncthreads();
    for (int s = 64; s > 0; s >>= 1) {
        if (threadIdx.x < s) red[threadIdx.x] += red[threadIdx.x + s];
        __syncthreads();
    }
    float inv = 1.0f / red[0];
    v.x *= inv; v.y *= inv; v.z *= inv; v.w *= inv;
    p[threadIdx.x] = v;
}

// ---------------- attn @ V: C[b,i,h*64+d] = sum_j P[bh,i,j] * V[b,j,h*64+d] -
// Tile 128x64x16, 256 threads, 8x4. grid (4,1,64)
__global__ __launch_bounds__(256)
void av_kernel(const float* __restrict__ P, const float* __restrict__ V,
               float* __restrict__ C) {
    __shared__ float As[16][128];
    __shared__ float Bs[16][64];

    int tid = threadIdx.x;
    int tx = tid & 15, ty = tid >> 4;
    int z = blockIdx.z;
    int b = z >> 3, h = z & 7;
    const float* pb = P + (size_t)z * SEQ * SEQ;
    const float* vb = V + (size_t)b * SEQ * DMODEL + h * DHEAD;
    float* cb = C + (size_t)b * SEQ * DMODEL + h * DHEAD;
    int row0 = blockIdx.x * 128;

    float acc[8][4];
#pragma unroll
    for (int i = 0; i < 8; i++)
#pragma unroll
        for (int j = 0; j < 4; j++) acc[i][j] = 0.0f;

    for (int k0 = 0; k0 < SEQ; k0 += 16) {
#pragma unroll
        for (int li = 0; li < 2; li++) {
            int idx = tid + li * 256;
            int r  = idx >> 2;
            int c4 = (idx & 3) * 4;
            float4 v = *(const float4*)&pb[(size_t)(row0 + r) * SEQ + k0 + c4];
            As[c4 + 0][r] = v.x; As[c4 + 1][r] = v.y;
            As[c4 + 2][r] = v.z; As[c4 + 3][r] = v.w;
        }
        {
            int r  = tid >> 4;
            int c4 = (tid & 15) * 4;
            *(float4*)&Bs[r][c4] = *(const float4*)&vb[(size_t)(k0 + r) * DMODEL + c4];
        }
        __syncthreads();
#pragma unroll
        for (int k = 0; k < 16; k++) {
            float a[8], bb[4];
#pragma unroll
            for (int i = 0; i < 8; i++) a[i]  = As[k][ty * 8 + i];
#pragma unroll
            for (int j = 0; j < 4; j++) bb[j] = Bs[k][tx * 4 + j];
#pragma unroll
            for (int i = 0; i < 8; i++)
#pragma unroll
                for (int j = 0; j < 4; j++) acc[i][j] += a[i] * bb[j];
        }
        __syncthreads();
    }

#pragma unroll
    for (int i = 0; i < 8; i++) {
        float4 o;
        o.x = acc[i][0]; o.y = acc[i][1]; o.z = acc[i][2]; o.w = acc[i][3];
        *(float4*)&cb[(size_t)(row0 + ty * 8 + i) * DMODEL + tx * 4] = o;
    }
}

// ---------------- residual + layernorm, one block per token row -------------
__global__ __launch_bounds__(128)
void ln_kernel(const float* __restrict__ x, const float* __restrict__ res,
               const float* __restrict__ gs, const float* __restrict__ gb,
               float* __restrict__ out) {
    __shared__ float red[128];
    int row = blockIdx.x;
    int t = threadIdx.x;
    float4 a = *(const float4*)&x  [(size_t)row * DMODEL + t * 4];
    float4 r = *(const float4*)&res[(size_t)row * DMODEL + t * 4];
    float y0 = a.x + r.x, y1 = a.y + r.y, y2 = a.z + r.z, y3 = a.w + r.w;

    red[t] = y0 + y1 + y2 + y3;
    __syncthreads();
    for (int s = 64; s > 0; s >>= 1) {
        if (t < s) red[t] += red[t + s];
        __syncthreads();
    }
    float mu = red[0] * (1.0f / DMODEL);
    __syncthreads();

    float d0 = y0 - mu, d1 = y1 - mu, d2 = y2 - mu, d3 = y3 - mu;
    red[t] = d0 * d0 + d1 * d1 + d2 * d2 + d3 * d3;
    __syncthreads();
    for (int s = 64; s > 0; s >>= 1) {
        if (t < s) red[t] += red[t + s];
        __syncthreads();
    }
    float k = rsqrtf(red[0] * (1.0f / DMODEL) + 1e-5f);

    float4 sv = *(const float4*)&gs[t * 4];
    float4 bv = *(const float4*)&gb[t * 4];
    float4 o;
    o.x = d0 * k * sv.x + bv.x;
    o.y = d1 * k * sv.y + bv.y;
    o.z = d2 * k * sv.z + bv.z;
    o.w = d3 * k * sv.w + bv.w;
    *(float4*)&out[(size_t)row * DMODEL + t * 4] = o;
}

// ---------------- host orchestration ----------------------------------------
static inline void launch_gemm(const float* A, const float* B, const float* bias,
                               float* C, int M, int N, int K, int epi,
                               float alpha, const float* pe) {
    dim3 grid(N / 64, M / 128);
    gemm_kernel<<<grid, 256>>>(A, B, bias, C, M, N, K, epi, alpha, pe);
}

extern "C" void kernel_launch(void* const* d_in, const int* in_sizes, int n_in,
                              void* d_out, int out_size) {
    const float* source = (const float*)d_in[0];
    // d_in[1] = mask (unused by reference)
    const float* fin_w1 = (const float*)d_in[2];
    const float* fin_b1 = (const float*)d_in[3];
    const float* fin_w2 = (const float*)d_in[4];
    const float* fin_b2 = (const float*)d_in[5];
    const float* wq = (const float*)d_in[6];
    const float* bq = (const float*)d_in[7];
    const float* wk = (const float*)d_in[8];
    const float* bk = (const float*)d_in[9];
    const float* wv = (const float*)d_in[10];
    const float* bv = (const float*)d_in[11];
    const float* wo = (const float*)d_in[12];
    const float* bo = (const float*)d_in[13];
    const float* n1s = (const float*)d_in[14];
    const float* n1b = (const float*)d_in[15];
    const float* ffw1 = (const float*)d_in[16];
    const float* ffb1 = (const float*)d_in[17];
    const float* ffw2 = (const float*)d_in[18];
    const float* ffb2 = (const float*)d_in[19];
    const float* n2s = (const float*)d_in[20];
    const float* n2b = (const float*)d_in[21];
    float* out = (float*)d_out;

    float *px, *pq, *pk, *pv, *pctx, *ptmp, *pffh, *psc, *ppe;
    cudaGetSymbolAddress((void**)&px,   g_x);
    cudaGetSymbolAddress((void**)&pq,   g_q);
    cudaGetSymbolAddress((void**)&pk,   g_k);
    cudaGetSymbolAddress((void**)&pv,   g_v);
    cudaGetSymbolAddress((void**)&pctx, g_ctx);
    cudaGetSymbolAddress((void**)&ptmp, g_tmp);
    cudaGetSymbolAddress((void**)&pffh, g_ffh);
    cudaGetSymbolAddress((void**)&psc,  g_sc);
    cudaGetSymbolAddress((void**)&ppe,  g_pe);

    const float sqrtd = 22.627416998f;        // sqrt(512)
    const float scale = 0.044194173824f;      // 1/sqrt(512)

    // positional encoding table
    pe_kernel<<<SEQ, 256>>>(ppe);

    // input FFN: relu(source @ fin_w1 + b1) @ fin_w2 + b2, * sqrt(d) + pe
    launch_gemm(source, fin_w1, fin_b1, pffh, MTOK, DFF, DIN, EPI_RELU, 0.f, nullptr);
    launch_gemm(pffh, fin_w2, fin_b2, px, MTOK, DMODEL, DFF, EPI_PE, sqrtd, ppe);

    for (int l = 0; l < NLAYER; l++) {
        const float* wql = wq + (size_t)l * DMODEL * DMODEL;
        const float* wkl = wk + (size_t)l * DMODEL * DMODEL;
        const float* wvl = wv + (size_t)l * DMODEL * DMODEL;
        const float* wol = wo + (size_t)l * DMODEL * DMODEL;
        const float* f1l = ffw1 + (size_t)l * DMODEL * DFF;
        const float* f2l = ffw2 + (size_t)l * DFF * DMODEL;

        launch_gemm(px, wql, bq + l * DMODEL, pq, MTOK, DMODEL, DMODEL, EPI_NONE, 0.f, nullptr);
        launch_gemm(px, wkl, bk + l * DMODEL, pk, MTOK, DMODEL, DMODEL, EPI_NONE, 0.f, nullptr);
        launch_gemm(px, wvl, bv + l * DMODEL, pv, MTOK, DMODEL, DMODEL, EPI_NONE, 0.f, nullptr);

        {
            dim3 grid(SEQ / 128, SEQ / 128, BATCH * NHEAD);
            qk_kernel<<<grid, 256>>>(pq, pk, psc, scale);
        }
        softmax_kernel<<<BATCH * NHEAD * SEQ, 128>>>(psc);
        {
            dim3 grid(SEQ / 128, 1, BATCH * NHEAD);
            av_kernel<<<grid, 256>>>(psc, pv, pctx);
        }

        launch_gemm(pctx, wol, bo + l * DMODEL, ptmp, MTOK, DMODEL, DMODEL, EPI_NONE, 0.f, nullptr);
        ln_kernel<<<MTOK, 128>>>(px, ptmp, n1s + l * DMODEL, n1b + l * DMODEL, px);

        launch_gemm(px, f1l, ffb1 + l * DFF, pffh, MTOK, DFF, DMODEL, EPI_RELU, 0.f, nullptr);
        launch_gemm(pffh, f2l, ffb2 + l * DMODEL, ptmp, MTOK, DMODEL, DFF, EPI_NONE, 0.f, nullptr);

        float* lnout = (l == NLAYER - 1) ? out : px;
        ln_kernel<<<MTOK, 128>>>(px, ptmp, n2s + l * DMODEL, n2b + l * DMODEL, lnout);
    }
}

// round 4
// speedup vs baseline: 1.0703x; 1.0703x over previous
#include <cuda_runtime.h>
#include <cuda_bf16.h>
#include <cstdint>
#include <math.h>

#define BATCH 8
#define SEQ 512
#define DMODEL 512
#define NHEAD 8
#define DHEAD 64
#define DFF 2048
#define NLAYER 6
#define DIN 64
#define MTOK (BATCH*SEQ)
#define BH (BATCH*NHEAD)
typedef __nv_bfloat16 bf16;

// row stride inside smem tiles: 72 bf16 = 144B (conflict-free ldmatrix)
#define TROW 144

__device__ __forceinline__ uint32_t smem_u32(const void* p){
    uint32_t a; asm("{ .reg .u64 t; cvta.to.shared.u64 t, %1; cvt.u32.u64 %0, t; }":"=r"(a):"l"(p)); return a;
}
__device__ __forceinline__ void ldsm4(uint32_t* r, uint32_t a){
    asm volatile("ldmatrix.sync.aligned.m8n8.x4.shared.b16 {%0,%1,%2,%3}, [%4];"
        : "=r"(r[0]),"=r"(r[1]),"=r"(r[2]),"=r"(r[3]) : "r"(a));
}
__device__ __forceinline__ void mma16816(float* d, const uint32_t* a, const uint32_t* b){
    asm volatile("mma.sync.aligned.m16n8k16.row.col.f32.bf16.bf16.f32 "
        "{%0,%1,%2,%3}, {%4,%5,%6,%7}, {%8,%9}, {%0,%1,%2,%3};"
        : "+f"(d[0]),"+f"(d[1]),"+f"(d[2]),"+f"(d[3])
        : "r"(a[0]),"r"(a[1]),"r"(a[2]),"r"(a[3]),"r"(b[0]),"r"(b[1]));
}
__device__ __forceinline__ void split2(float f, bf16&h, bf16&l){
    h=__float2bfloat16(f); l=__float2bfloat16(f-__bfloat162float(h));
}

// ---------- scratch ----------
__device__ float g_pe[SEQ*DMODEL];
__device__ float g_x[MTOK*DMODEL];
__device__ float g_tmp[MTOK*DMODEL];
__device__ float g_sumr[BH*SEQ];
__device__ float g_sc[(size_t)BH*SEQ*SEQ];
__device__ bf16 g_srch[MTOK*DIN], g_srcl[MTOK*DIN];
__device__ bf16 g_xh[MTOK*DMODEL], g_xl[MTOK*DMODEL];
__device__ bf16 g_qh[MTOK*DMODEL], g_ql[MTOK*DMODEL];
__device__ bf16 g_kh[MTOK*DMODEL], g_kl[MTOK*DMODEL];
__device__ bf16 g_vth[BH*DHEAD*SEQ], g_vtl[BH*DHEAD*SEQ];
__device__ bf16 g_ch[MTOK*DMODEL], g_cl[MTOK*DMODEL];
__device__ bf16 g_fh[MTOK*DFF], g_fl[MTOK*DFF];
__device__ bf16 g_ph[(size_t)BH*SEQ*SEQ], g_pl[(size_t)BH*SEQ*SEQ];
__device__ bf16 g_fw1h[DFF*DIN], g_fw1l[DFF*DIN];
__device__ bf16 g_fw2h[DMODEL*DFF], g_fw2l[DMODEL*DFF];
__device__ bf16 g_wqh[NLAYER*DMODEL*DMODEL], g_wqlo[NLAYER*DMODEL*DMODEL];
__device__ bf16 g_wkh[NLAYER*DMODEL*DMODEL], g_wklo[NLAYER*DMODEL*DMODEL];
__device__ bf16 g_wvh[NLAYER*DMODEL*DMODEL], g_wvlo[NLAYER*DMODEL*DMODEL];
__device__ bf16 g_woh[NLAYER*DMODEL*DMODEL], g_wolo[NLAYER*DMODEL*DMODEL];
__device__ bf16 g_f1h[NLAYER*DFF*DMODEL], g_f1l[NLAYER*DFF*DMODEL];
__device__ bf16 g_f2h[NLAYER*DMODEL*DFF], g_f2l[NLAYER*DMODEL*DFF];

// ---------- prep ----------
__global__ void pe_kernel(float* __restrict__ pe){
    int s=blockIdx.x, i=threadIdx.x;
    float dv=expf(-(float)(2*i)*(logf(10000.0f)/(float)DMODEL));
    float a=(float)s*dv;
    pe[s*DMODEL+2*i]=sinf(a); pe[s*DMODEL+2*i+1]=cosf(a);
}
__global__ void src_split_kernel(const float* __restrict__ s, bf16* __restrict__ oh, bf16* __restrict__ ol, int n){
    int i=blockIdx.x*blockDim.x+threadIdx.x;
    if(i<n){ bf16 h,l; split2(s[i],h,l); oh[i]=h; ol[i]=l; }
}
// W[K,N] row-major -> [N,K] hi/lo
__global__ void tsplit_kernel(const float* __restrict__ W, bf16* __restrict__ Oh, bf16* __restrict__ Ol, int K, int N){
    __shared__ float t[32][33];
    const float* w=W+(size_t)blockIdx.z*K*N;
    bf16* oh=Oh+(size_t)blockIdx.z*K*N; bf16* ol=Ol+(size_t)blockIdx.z*K*N;
    int n0=blockIdx.x*32, k0=blockIdx.y*32, tx=threadIdx.x, ty=threadIdx.y;
#pragma unroll
    for(int i=0;i<32;i+=8) t[ty+i][tx]=w[(size_t)(k0+ty+i)*N+n0+tx];
    __syncthreads();
#pragma unroll
    for(int i=0;i<32;i+=8){
        bf16 h,l; split2(t[tx][ty+i],h,l);
        oh[(size_t)(n0+ty+i)*K+k0+tx]=h; ol[(size_t)(n0+ty+i)*K+k0+tx]=l;
    }
}

// tile loader: nrows x 64 bf16 into padded 144B-stride smem
__device__ __forceinline__ void load_tile(char* dst, const bf16* __restrict__ src,
                                          int row0, int k0, int ld, int nrows, int nthr){
    for(int idx=threadIdx.x; idx<nrows*8; idx+=nthr){
        int r=idx>>3, c8=idx&7;
        *(uint4*)(dst + r*TROW + c8*16) = *(const uint4*)(src + (size_t)(row0+r)*ld + k0 + c8*8);
    }
}

// one K-64 chunk of bf16x3 mma. acc[4*NI][4]; warp tile M64 x (NI*8*? ...) N = NI*8*2? no: NI tiles of n8.
template<int NI>
__device__ __forceinline__ void mma_chunk(uint32_t sa, uint32_t sal, uint32_t sb, uint32_t sbl,
                                          float (*acc)[4], int lane, int wm, int wn){
    int ar=(lane&7)+((lane>>3)&1)*8, abit=((lane>>4)&1)*8;
    int br=(lane&7)+((lane>>4)&1)*8, bbit=((lane>>3)&1)*8;
#pragma unroll
    for(int kk=0;kk<4;kk++){
        uint32_t ah[4][4], al[4][4], bh[NI][2], bl[NI][2];
        int ac=kk*16+abit, bc=kk*16+bbit;
#pragma unroll
        for(int mi=0;mi<4;mi++){
            uint32_t off=(uint32_t)((wm+mi*16+ar)*TROW + ac*2);
            ldsm4(ah[mi], sa+off); ldsm4(al[mi], sal+off);
        }
#pragma unroll
        for(int nj=0;nj<NI/2;nj++){
            uint32_t off=(uint32_t)((wn+nj*16+br)*TROW + bc*2);
            uint32_t r[4];
            ldsm4(r, sb+off);  bh[nj*2][0]=r[0]; bh[nj*2][1]=r[1]; bh[nj*2+1][0]=r[2]; bh[nj*2+1][1]=r[3];
            ldsm4(r, sbl+off); bl[nj*2][0]=r[0]; bl[nj*2][1]=r[1]; bl[nj*2+1][0]=r[2]; bl[nj*2+1][1]=r[3];
        }
#pragma unroll
        for(int mi=0;mi<4;mi++)
#pragma unroll
            for(int ni=0;ni<NI;ni++){
                float* d=acc[mi*NI+ni];
                mma16816(d, ah[mi], bh[ni]);
                mma16816(d, al[mi], bh[ni]);
                mma16816(d, ah[mi], bl[ni]);
            }
    }
}

// ---------- generic GEMM 128x128, warps 2x4 (M64 x N32) ----------
// epi: 0 bias->hi/lo | 1 bias,relu->hi/lo | 2 bias->V^T hi/lo | 3 bias->f32 | 4 bias,*alpha,+pe->f32+hi/lo
#define GSA 0
#define GSAL 18432
#define GSB 36864
#define GSBL 55296
#define GTOT 73728
__global__ __launch_bounds__(256)
void gemm_bf3(const bf16* __restrict__ Ah, const bf16* __restrict__ Al, int lda,
              const bf16* __restrict__ Bh, const bf16* __restrict__ Bl, int K,
              const float* __restrict__ bias, int epi,
              float* __restrict__ of, bf16* __restrict__ oh, bf16* __restrict__ ol,
              int ldc, float alpha, const float* __restrict__ pe){
    extern __shared__ char smem[];
    uint32_t sb0=smem_u32(smem);
    int tid=threadIdx.x, wid=tid>>5, lane=tid&31;
    int row0=blockIdx.y*128, col0=blockIdx.x*128;
    int wm=(wid>>2)*64, wn=(wid&3)*32;
    float acc[16][4];
#pragma unroll
    for(int i=0;i<16;i++){ acc[i][0]=0;acc[i][1]=0;acc[i][2]=0;acc[i][3]=0; }
    for(int kc=0;kc<K/64;kc++){
        int k0=kc*64;
        load_tile(smem+GSA,  Ah,row0,k0,lda,128,256);
        load_tile(smem+GSAL, Al,row0,k0,lda,128,256);
        load_tile(smem+GSB,  Bh,col0,k0,K,128,256);
        load_tile(smem+GSBL, Bl,col0,k0,K,128,256);
        __syncthreads();
        mma_chunk<4>(sb0+GSA,sb0+GSAL,sb0+GSB,sb0+GSBL,acc,lane,wm,wn);
        __syncthreads();
    }
    int gid=lane>>2, tig=lane&3;
#pragma unroll
    for(int mi=0;mi<4;mi++)
#pragma unroll
    for(int ni=0;ni<4;ni++){
        float* d=acc[mi*4+ni];
#pragma unroll
        for(int hf=0;hf<2;hf++){
            int r=row0+wm+mi*16+gid+hf*8;
            int c=col0+wn+ni*8+tig*2;
            float v0=d[hf*2]+__ldg(&bias[c]), v1=d[hf*2+1]+__ldg(&bias[c+1]);
            if(epi==1){ v0=fmaxf(v0,0.f); v1=fmaxf(v1,0.f); }
            if(epi==4){
                const float* per=pe+(size_t)(r&(SEQ-1))*DMODEL+c;
                v0=v0*alpha+per[0]; v1=v1*alpha+per[1];
            }
            if(epi==3||epi==4) *(float2*)(of+(size_t)r*ldc+c)=make_float2(v0,v1);
            if(epi==0||epi==1||epi==4){
                bf16 h0,l0,h1,l1; split2(v0,h0,l0); split2(v1,h1,l1);
                __nv_bfloat162 H{h0,h1}, L{l0,l1};
                *(__nv_bfloat162*)(oh+(size_t)r*ldc+c)=H;
                *(__nv_bfloat162*)(ol+(size_t)r*ldc+c)=L;
            }
            if(epi==2){
                int b=r>>9, s=r&(SEQ-1);
#pragma unroll
                for(int u=0;u<2;u++){
                    int n=c+u; float v=u?v1:v0;
                    size_t off=((size_t)(b*NHEAD+(n>>6))*DHEAD+(n&63))*SEQ+s;
                    bf16 hh,ll; split2(v,hh,ll); oh[off]=hh; ol[off]=ll;
                }
            }
        }
    }
}

// ---------- QK^T -> f32 scores (scaled). grid(4,4,BH) ----------
__global__ __launch_bounds__(256)
void qk_kernel(const bf16* __restrict__ qh, const bf16* __restrict__ ql,
               const bf16* __restrict__ kh, const bf16* __restrict__ kl,
               float* __restrict__ sc, float scale){
    extern __shared__ char smem[];
    uint32_t sb0=smem_u32(smem);
    int tid=threadIdx.x, wid=tid>>5, lane=tid&31;
    int z=blockIdx.z, b=z>>3, h=z&7;
    int row0=blockIdx.y*128, col0=blockIdx.x*128, k0=h*DHEAD;
    int wm=(wid>>2)*64, wn=(wid&3)*32;
    float acc[16][4];
#pragma unroll
    for(int i=0;i<16;i++){ acc[i][0]=0;acc[i][1]=0;acc[i][2]=0;acc[i][3]=0; }
    load_tile(smem+GSA,  qh,b*SEQ+row0,k0,DMODEL,128,256);
    load_tile(smem+GSAL, ql,b*SEQ+row0,k0,DMODEL,128,256);
    load_tile(smem+GSB,  kh,b*SEQ+col0,k0,DMODEL,128,256);
    load_tile(smem+GSBL, kl,b*SEQ+col0,k0,DMODEL,128,256);
    __syncthreads();
    mma_chunk<4>(sb0+GSA,sb0+GSAL,sb0+GSB,sb0+GSBL,acc,lane,wm,wn);
    int gid=lane>>2, tig=lane&3;
    float* eb=sc+(size_t)z*SEQ*SEQ;
#pragma unroll
    for(int mi=0;mi<4;mi++)
#pragma unroll
    for(int ni=0;ni<4;ni++){
        float* d=acc[mi*4+ni];
#pragma unroll
        for(int hf=0;hf<2;hf++){
            int r=row0+wm+mi*16+gid+hf*8, c=col0+wn+ni*8+tig*2;
            *(float2*)(eb+(size_t)r*SEQ+c)=make_float2(d[hf*2]*scale,d[hf*2+1]*scale);
        }
    }
}

// ---------- softmax row -> unnormalized exp hi/lo + 1/sum ----------
__global__ __launch_bounds__(128)
void softmax_kernel(const float* __restrict__ sc, bf16* __restrict__ ph, bf16* __restrict__ pl,
                    float* __restrict__ sumr){
    __shared__ float red[128];
    int row=blockIdx.x, t=threadIdx.x;
    const float4* p=(const float4*)(sc+(size_t)row*SEQ);
    float4 v=p[t];
    float m=fmaxf(fmaxf(v.x,v.y),fmaxf(v.z,v.w));
    red[t]=m; __syncthreads();
    for(int s=64;s>0;s>>=1){ if(t<s) red[t]=fmaxf(red[t],red[t+s]); __syncthreads(); }
    m=red[0]; __syncthreads();
    float e0=__expf(v.x-m), e1=__expf(v.y-m), e2=__expf(v.z-m), e3=__expf(v.w-m);
    red[t]=e0+e1+e2+e3; __syncthreads();
    for(int s=64;s>0;s>>=1){ if(t<s) red[t]+=red[t+s]; __syncthreads(); }
    if(t==0) sumr[row]=1.0f/red[0];
    size_t off=(size_t)row*SEQ+t*4;
    bf16 h0,l0,h1,l1,h2,l2,h3,l3;
    split2(e0,h0,l0); split2(e1,h1,l1); split2(e2,h2,l2); split2(e3,h3,l3);
    __nv_bfloat162 H0{h0,h1},H1{h2,h3},L0{l0,l1},L1{l2,l3};
    *(__nv_bfloat162*)(ph+off)=H0; *(__nv_bfloat162*)(ph+off+2)=H1;
    *(__nv_bfloat162*)(pl+off)=L0; *(__nv_bfloat162*)(pl+off+2)=L1;
}

// ---------- attn @ V. grid(4,BH). warps 2x4 (M64 x N16), NI=2 ----------
#define ASA 0
#define ASAL 18432
#define ASB 36864
#define ASBL 46080
#define ATOT 55296
__global__ __launch_bounds__(256)
void av_bf3(const bf16* __restrict__ ph, const bf16* __restrict__ pl,
            const bf16* __restrict__ vth, const bf16* __restrict__ vtl,
            const float* __restrict__ sumr, bf16* __restrict__ ch, bf16* __restrict__ cl){
    extern __shared__ char smem[];
    uint32_t sb0=smem_u32(smem);
    int tid=threadIdx.x, wid=tid>>5, lane=tid&31;
    int z=blockIdx.y, b=z>>3, h=z&7;
    int row0=blockIdx.x*128;
    int wm=(wid>>2)*64, wn=(wid&3)*16;
    float acc[8][4];
#pragma unroll
    for(int i=0;i<8;i++){ acc[i][0]=0;acc[i][1]=0;acc[i][2]=0;acc[i][3]=0; }
    const bf16* pbh=ph+(size_t)z*SEQ*SEQ;
    const bf16* pbl=pl+(size_t)z*SEQ*SEQ;
    for(int kc=0;kc<8;kc++){
        int k0=kc*64;
        load_tile(smem+ASA,  pbh,row0,k0,SEQ,128,256);
        load_tile(smem+ASAL, pbl,row0,k0,SEQ,128,256);
        load_tile(smem+ASB,  vth,z*DHEAD,k0,SEQ,64,256);
        load_tile(smem+ASBL, vtl,z*DHEAD,k0,SEQ,64,256);
        __syncthreads();
        mma_chunk<2>(sb0+ASA,sb0+ASAL,sb0+ASB,sb0+ASBL,acc,lane,wm,wn);
        __syncthreads();
    }
    int gid=lane>>2, tig=lane&3;
#pragma unroll
    for(int mi=0;mi<4;mi++)
#pragma unroll
    for(int ni=0;ni<2;ni++){
        float* d=acc[mi*2+ni];
#pragma unroll
        for(int hf=0;hf<2;hf++){
            int rl=row0+wm+mi*16+gid+hf*8;
            float inv=sumr[(size_t)z*SEQ+rl];
            int token=b*SEQ+rl, c=wn+ni*8+tig*2;
            float v0=d[hf*2]*inv, v1=d[hf*2+1]*inv;
            bf16 h0,l0,h1,l1; split2(v0,h0,l0); split2(v1,h1,l1);
            __nv_bfloat162 H{h0,h1}, L{l0,l1};
            size_t off=(size_t)token*DMODEL+h*DHEAD+c;
            *(__nv_bfloat162*)(ch+off)=H; *(__nv_bfloat162*)(cl+off)=L;
        }
    }
}

// ---------- residual + LN -> f32 + hi/lo ----------
__global__ __launch_bounds__(128)
void ln_kernel(const float* __restrict__ x, const float* __restrict__ res,
               const float* __restrict__ gs, const float* __restrict__ gb,
               float* __restrict__ out, bf16* __restrict__ oh, bf16* __restrict__ ol){
    __shared__ float red[128];
    int row=blockIdx.x, t=threadIdx.x;
    float4 a=*(const float4*)&x[(size_t)row*DMODEL+t*4];
    float4 r=*(const float4*)&res[(size_t)row*DMODEL+t*4];
    float y0=a.x+r.x, y1=a.y+r.y, y2=a.z+r.z, y3=a.w+r.w;
    red[t]=y0+y1+y2+y3; __syncthreads();
    for(int s=64;s>0;s>>=1){ if(t<s) red[t]+=red[t+s]; __syncthreads(); }
    float mu=red[0]*(1.0f/DMODEL); __syncthreads();
    float d0=y0-mu,d1=y1-mu,d2=y2-mu,d3=y3-mu;
    red[t]=d0*d0+d1*d1+d2*d2+d3*d3; __syncthreads();
    for(int s=64;s>0;s>>=1){ if(t<s) red[t]+=red[t+s]; __syncthreads(); }
    float k=rsqrtf(red[0]*(1.0f/DMODEL)+1e-5f);
    float4 sv=*(const float4*)&gs[t*4], bv=*(const float4*)&gb[t*4];
    float o0=d0*k*sv.x+bv.x, o1=d1*k*sv.y+bv.y, o2=d2*k*sv.z+bv.z, o3=d3*k*sv.w+bv.w;
    *(float4*)&out[(size_t)row*DMODEL+t*4]=make_float4(o0,o1,o2,o3);
    size_t off=(size_t)row*DMODEL+t*4;
    bf16 h0,l0,h1,l1,h2,l2,h3,l3;
    split2(o0,h0,l0); split2(o1,h1,l1); split2(o2,h2,l2); split2(o3,h3,l3);
    __nv_bfloat162 H0{h0,h1},H1{h2,h3},L0{l0,l1},L1{l2,l3};
    *(__nv_bfloat162*)(oh+off)=H0; *(__nv_bfloat162*)(oh+off+2)=H1;
    *(__nv_bfloat162*)(ol+off)=L0; *(__nv_bfloat162*)(ol+off+2)=L1;
}

// ---------- host ----------
#define GETP(sym,p,T) do{ void* _t; cudaGetSymbolAddress(&_t,sym); p=(T*)_t; }while(0)

extern "C" void kernel_launch(void* const* d_in, const int* in_sizes, int n_in,
                              void* d_out, int out_size){
    const float* source=(const float*)d_in[0];
    const float* fin_w1=(const float*)d_in[2];
    const float* fin_b1=(const float*)d_in[3];
    const float* fin_w2=(const float*)d_in[4];
    const float* fin_b2=(const float*)d_in[5];
    const float* wq=(const float*)d_in[6];  const float* bq=(const float*)d_in[7];
    const float* wk=(const float*)d_in[8];  const float* bk=(const float*)d_in[9];
    const float* wv=(const float*)d_in[10]; const float* bvv=(const float*)d_in[11];
    const float* wo=(const float*)d_in[12]; const float* bo=(const float*)d_in[13];
    const float* n1s=(const float*)d_in[14]; const float* n1b=(const float*)d_in[15];
    const float* ffw1=(const float*)d_in[16]; const float* ffb1=(const float*)d_in[17];
    const float* ffw2=(const float*)d_in[18]; const float* ffb2=(const float*)d_in[19];
    const float* n2s=(const float*)d_in[20]; const float* n2b=(const float*)d_in[21];
    float* out=(float*)d_out;

    float *ppe,*px,*ptmp,*psumr,*psc;
    GETP(g_pe,ppe,float); GETP(g_x,px,float); GETP(g_tmp,ptmp,float);
    GETP(g_sumr,psumr,float); GETP(g_sc,psc,float);
    bf16 *srch,*srcl,*xh,*xl,*qh,*ql,*kh,*kl,*vth,*vtl,*chh,*cll,*fhh,*fll,*phh,*pll;
    GETP(g_srch,srch,bf16); GETP(g_srcl,srcl,bf16);
    GETP(g_xh,xh,bf16); GETP(g_xl,xl,bf16);
    GETP(g_qh,qh,bf16); GETP(g_ql,ql,bf16);
    GETP(g_kh,kh,bf16); GETP(g_kl,kl,bf16);
    GETP(g_vth,vth,bf16); GETP(g_vtl,vtl,bf16);
    GETP(g_ch,chh,bf16); GETP(g_cl,cll,bf16);
    GETP(g_fh,fhh,bf16); GETP(g_fl,fll,bf16);
    GETP(g_ph,phh,bf16); GETP(g_pl,pll,bf16);
    bf16 *fw1h,*fw1l,*fw2h,*fw2l,*wqh,*wqlo,*wkh,*wklo,*wvh,*wvlo,*woh,*wolo,*f1h,*f1l,*f2h,*f2l;
    GETP(g_fw1h,fw1h,bf16); GETP(g_fw1l,fw1l,bf16);
    GETP(g_fw2h,fw2h,bf16); GETP(g_fw2l,fw2l,bf16);
    GETP(g_wqh,wqh,bf16); GETP(g_wqlo,wqlo,bf16);
    GETP(g_wkh,wkh,bf16); GETP(g_wklo,wklo,bf16);
    GETP(g_wvh,wvh,bf16); GETP(g_wvlo,wvlo,bf16);
    GETP(g_woh,woh,bf16); GETP(g_wolo,wolo,bf16);
    GETP(g_f1h,f1h,bf16); GETP(g_f1l,f1l,bf16);
    GETP(g_f2h,f2h,bf16); GETP(g_f2l,f2l,bf16);

    cudaFuncSetAttribute(gemm_bf3, cudaFuncAttributeMaxDynamicSharedMemorySize, GTOT);
    cudaFuncSetAttribute(qk_kernel, cudaFuncAttributeMaxDynamicSharedMemorySize, GTOT);
    cudaFuncSetAttribute(av_bf3,   cudaFuncAttributeMaxDynamicSharedMemorySize, ATOT);

    const float sqrtd=22.627416998f, scale=0.044194173824f;

    pe_kernel<<<SEQ,256>>>(ppe);
    src_split_kernel<<<(MTOK*DIN+255)/256,256>>>(source,srch,srcl,MTOK*DIN);
    {
        dim3 blk(32,8);
        tsplit_kernel<<<dim3(DFF/32,DIN/32,1),blk>>>(fin_w1,fw1h,fw1l,DIN,DFF);
        tsplit_kernel<<<dim3(DMODEL/32,DFF/32,1),blk>>>(fin_w2,fw2h,fw2l,DFF,DMODEL);
        tsplit_kernel<<<dim3(16,16,NLAYER),blk>>>(wq,wqh,wqlo,DMODEL,DMODEL);
        tsplit_kernel<<<dim3(16,16,NLAYER),blk>>>(wk,wkh,wklo,DMODEL,DMODEL);
        tsplit_kernel<<<dim3(16,16,NLAYER),blk>>>(wv,wvh,wvlo,DMODEL,DMODEL);
        tsplit_kernel<<<dim3(16,16,NLAYER),blk>>>(wo,woh,wolo,DMODEL,DMODEL);
        tsplit_kernel<<<dim3(DFF/32,DMODEL/32,NLAYER),blk>>>(ffw1,f1h,f1l,DMODEL,DFF);
        tsplit_kernel<<<dim3(DMODEL/32,DFF/32,NLAYER),blk>>>(ffw2,f2h,f2l,DFF,DMODEL);
    }

    gemm_bf3<<<dim3(16,32),256,GTOT>>>(srch,srcl,DIN,fw1h,fw1l,DIN,fin_b1,1,nullptr,fhh,fll,DFF,0.f,nullptr);
    gemm_bf3<<<dim3(4,32),256,GTOT>>>(fhh,fll,DFF,fw2h,fw2l,DFF,fin_b2,4,px,xh,xl,DMODEL,sqrtd,ppe);

    for(int l=0;l<NLAYER;l++){
        size_t w5=(size_t)l*DMODEL*DMODEL;
        size_t wf1=(size_t)l*DFF*DMODEL, wf2=(size_t)l*DMODEL*DFF;

        gemm_bf3<<<dim3(4,32),256,GTOT>>>(xh,xl,DMODEL,wqh+w5,wqlo+w5,DMODEL,bq+l*DMODEL,0,nullptr,qh,ql,DMODEL,0.f,nullptr);
        gemm_bf3<<<dim3(4,32),256,GTOT>>>(xh,xl,DMODEL,wkh+w5,wklo+w5,DMODEL,bk+l*DMODEL,0,nullptr,kh,kl,DMODEL,0.f,nullptr);
        gemm_bf3<<<dim3(4,32),256,GTOT>>>(xh,xl,DMODEL,wvh+w5,wvlo+w5,DMODEL,bvv+l*DMODEL,2,nullptr,vth,vtl,DMODEL,0.f,nullptr);

        qk_kernel<<<dim3(4,4,BH),256,GTOT>>>(qh,ql,kh,kl,psc,scale);
        softmax_kernel<<<BH*SEQ,128>>>(psc,phh,pll,psumr);
        av_bf3<<<dim3(4,BH),256,ATOT>>>(phh,pll,vth,vtl,psumr,chh,cll);

        gemm_bf3<<<dim3(4,32),256,GTOT>>>(chh,cll,DMODEL,woh+w5,wolo+w5,DMODEL,bo+l*DMODEL,3,ptmp,nullptr,nullptr,DMODEL,0.f,nullptr);
        ln_kernel<<<MTOK,128>>>(px,ptmp,n1s+l*DMODEL,n1b+l*DMODEL,px,xh,xl);

        gemm_bf3<<<dim3(16,32),256,GTOT>>>(xh,xl,DMODEL,f1h+wf1,f1l+wf1,DMODEL,ffb1+l*DFF,1,nullptr,fhh,fll,DFF,0.f,nullptr);
        gemm_bf3<<<dim3(4,32),256,GTOT>>>(fhh,fll,DFF,f2h+wf2,f2l+wf2,DFF,ffb2+l*DMODEL,3,ptmp,nullptr,nullptr,DMODEL,0.f,nullptr);

        float* lnout=(l==NLAYER-1)?out:px;
        ln_kernel<<<MTOK,128>>>(px,ptmp,n2s+l*DMODEL,n2b+l*DMODEL,lnout,xh,xl);
    }
}

// round 6
// speedup vs baseline: 2.2462x; 2.0986x over previous
#include <cuda_runtime.h>
#include <cuda_bf16.h>
#include <cstdint>
#include <math.h>

#define BATCH 8
#define SEQ 512
#define DMODEL 512
#define NHEAD 8
#define DHEAD 64
#define DFF 2048
#define NLAYER 6
#define DIN 64
#define MTOK (BATCH*SEQ)
#define BH (BATCH*NHEAD)
typedef __nv_bfloat16 bf16;

#define TROW 144   // 72 bf16 per row, conflict-free ldmatrix

__device__ __forceinline__ uint32_t smem_u32(const void* p){
    uint32_t a; asm("{ .reg .u64 t; cvta.to.shared.u64 t, %1; cvt.u32.u64 %0, t; }":"=r"(a):"l"(p)); return a;
}
__device__ __forceinline__ void ldsm4(uint32_t* r, uint32_t a){
    asm volatile("ldmatrix.sync.aligned.m8n8.x4.shared.b16 {%0,%1,%2,%3}, [%4];"
        : "=r"(r[0]),"=r"(r[1]),"=r"(r[2]),"=r"(r[3]) : "r"(a));
}
__device__ __forceinline__ void mma16816(float* d, const uint32_t* a, const uint32_t* b){
    asm volatile("mma.sync.aligned.m16n8k16.row.col.f32.bf16.bf16.f32 "
        "{%0,%1,%2,%3}, {%4,%5,%6,%7}, {%8,%9}, {%0,%1,%2,%3};"
        : "+f"(d[0]),"+f"(d[1]),"+f"(d[2]),"+f"(d[3])
        : "r"(a[0]),"r"(a[1]),"r"(a[2]),"r"(a[3]),"r"(b[0]),"r"(b[1]));
}
__device__ __forceinline__ void split2(float f, bf16&h, bf16&l){
    h=__float2bfloat16(f); l=__float2bfloat16(f-__bfloat162float(h));
}
#define CP16(dst,src) asm volatile("cp.async.cg.shared.global [%0], [%1], 16;"::"r"(dst),"l"(src))
#define CP_COMMIT() asm volatile("cp.async.commit_group;":::"memory")
#define CP_WAIT0() asm volatile("cp.async.wait_group 0;":::"memory")
#define CP_WAIT1() asm volatile("cp.async.wait_group 1;":::"memory")

// ---------- scratch ----------
__device__ float g_pe[SEQ*DMODEL];
__device__ float g_x[MTOK*DMODEL];
__device__ float g_tmp[MTOK*DMODEL];
__device__ float g_sumr[BH*SEQ];
__device__ float g_sc[(size_t)BH*SEQ*SEQ];
__device__ bf16 g_srch[MTOK*DIN], g_srcl[MTOK*DIN];
__device__ bf16 g_xh[MTOK*DMODEL], g_xl[MTOK*DMODEL];
__device__ bf16 g_qh[MTOK*DMODEL], g_ql[MTOK*DMODEL];
__device__ bf16 g_kh[MTOK*DMODEL], g_kl[MTOK*DMODEL];
__device__ bf16 g_vth[BH*DHEAD*SEQ], g_vtl[BH*DHEAD*SEQ];
__device__ bf16 g_ch[MTOK*DMODEL], g_cl[MTOK*DMODEL];
__device__ bf16 g_fh[MTOK*DFF], g_fl[MTOK*DFF];
__device__ bf16 g_ph[(size_t)BH*SEQ*SEQ], g_pl[(size_t)BH*SEQ*SEQ];
__device__ bf16 g_fw1h[DFF*DIN], g_fw1l[DFF*DIN];
__device__ bf16 g_fw2h[DMODEL*DFF], g_fw2l[DMODEL*DFF];
__device__ bf16 g_wqh[NLAYER*DMODEL*DMODEL], g_wqlo[NLAYER*DMODEL*DMODEL];
__device__ bf16 g_wkh[NLAYER*DMODEL*DMODEL], g_wklo[NLAYER*DMODEL*DMODEL];
__device__ bf16 g_wvh[NLAYER*DMODEL*DMODEL], g_wvlo[NLAYER*DMODEL*DMODEL];
__device__ bf16 g_woh[NLAYER*DMODEL*DMODEL], g_wolo[NLAYER*DMODEL*DMODEL];
__device__ bf16 g_f1h[NLAYER*DFF*DMODEL], g_f1l[NLAYER*DFF*DMODEL];
__device__ bf16 g_f2h[NLAYER*DMODEL*DFF], g_f2l[NLAYER*DMODEL*DFF];

// ---------- consolidated weight transpose+split (one launch) ----------
__device__ __forceinline__ void do_tsplit(const float* __restrict__ W, bf16* __restrict__ Oh,
                                          bf16* __restrict__ Ol, int K, int N, int z, int bx, int by){
    __shared__ float t[32][33];
    const float* w=W+(size_t)z*K*N;
    bf16* oh=Oh+(size_t)z*K*N; bf16* ol=Ol+(size_t)z*K*N;
    int n0=bx*32, k0=by*32, tx=threadIdx.x, ty=threadIdx.y;
#pragma unroll
    for(int i=0;i<32;i+=8) t[ty+i][tx]=w[(size_t)(k0+ty+i)*N+n0+tx];
    __syncthreads();
#pragma unroll
    for(int i=0;i<32;i+=8){
        bf16 h,l; split2(t[tx][ty+i],h,l);
        oh[(size_t)(n0+ty+i)*K+k0+tx]=h; ol[(size_t)(n0+ty+i)*K+k0+tx]=l;
    }
}
// block counts: fw1:128 | fw2:1024 | wq/wk/wv/wo:1536 each | ffw1:6144 | ffw2:6144
__global__ void tsplit_all(const float* fin_w1, const float* fin_w2,
    const float* wq, const float* wk, const float* wv, const float* wo,
    const float* ffw1, const float* ffw2,
    bf16* fw1h, bf16* fw1l, bf16* fw2h, bf16* fw2l,
    bf16* wqh, bf16* wqlo, bf16* wkh, bf16* wklo,
    bf16* wvh, bf16* wvlo, bf16* woh, bf16* wolo,
    bf16* f1h, bf16* f1l, bf16* f2h, bf16* f2l){
    int bid=blockIdx.x;
    if(bid<128){ int i=bid; do_tsplit(fin_w1,fw1h,fw1l,DIN,DFF,0,i%64,i/64); return; } bid-=128;
    if(bid<1024){ int i=bid; do_tsplit(fin_w2,fw2h,fw2l,DFF,DMODEL,0,i%16,i/16); return; } bid-=1024;
    if(bid<1536){ int i=bid; do_tsplit(wq,wqh,wqlo,DMODEL,DMODEL,i/256,(i%256)%16,(i%256)/16); return; } bid-=1536;
    if(bid<1536){ int i=bid; do_tsplit(wk,wkh,wklo,DMODEL,DMODEL,i/256,(i%256)%16,(i%256)/16); return; } bid-=1536;
    if(bid<1536){ int i=bid; do_tsplit(wv,wvh,wvlo,DMODEL,DMODEL,i/256,(i%256)%16,(i%256)/16); return; } bid-=1536;
    if(bid<1536){ int i=bid; do_tsplit(wo,woh,wolo,DMODEL,DMODEL,i/256,(i%256)%16,(i%256)/16); return; } bid-=1536;
    if(bid<6144){ int i=bid; do_tsplit(ffw1,f1h,f1l,DMODEL,DFF,i/1024,(i%1024)%64,(i%1024)/64); return; } bid-=6144;
    { int i=bid; do_tsplit(ffw2,f2h,f2l,DFF,DMODEL,i/1024,(i%1024)%16,(i%1024)/16); }
}
#define TSPLIT_BLOCKS (128+1024+4*1536+6144+6144)

// ---------- pe table + source split (one launch) ----------
__global__ void prep_misc(float* __restrict__ pe, const float* __restrict__ src,
                          bf16* __restrict__ sh, bf16* __restrict__ sl){
    int bid=blockIdx.x, t=threadIdx.x;
    if(bid<SEQ){
        float dv=expf(-(float)(2*t)*(logf(10000.0f)/(float)DMODEL));
        float a=(float)bid*dv;
        pe[bid*DMODEL+2*t]=sinf(a); pe[bid*DMODEL+2*t+1]=cosf(a);
    } else {
        int i=(bid-SEQ)*256+t;
        if(i<MTOK*DIN){ bf16 h,l; split2(src[i],h,l); sh[i]=h; sl[i]=l; }
    }
}

// ---------- cp.async tile loader: nrows x 64 bf16 into TROW-stride smem ----------
__device__ __forceinline__ void load_cp(uint32_t dst, const bf16* __restrict__ src,
                                        int row0, int k0, int ld, int nrows){
    for(int idx=threadIdx.x; idx<nrows*8; idx+=256){
        int r=idx>>3, c8=idx&7;
        CP16(dst + r*TROW + c8*16, src + (size_t)(row0+r)*ld + k0 + c8*8);
    }
}

// one K-64 chunk of bf16x3 mma
template<int NI>
__device__ __forceinline__ void mma_chunk(uint32_t sa, uint32_t sal, uint32_t sb, uint32_t sbl,
                                          float (*acc)[4], int lane, int wm, int wn){
    int ar=(lane&7)+((lane>>3)&1)*8, abit=((lane>>4)&1)*8;
    int br=(lane&7)+((lane>>4)&1)*8, bbit=((lane>>3)&1)*8;
#pragma unroll
    for(int kk=0;kk<4;kk++){
        uint32_t ah[4][4], al[4][4], bh[NI][2], bl[NI][2];
        int ac=kk*16+abit, bc=kk*16+bbit;
#pragma unroll
        for(int mi=0;mi<4;mi++){
            uint32_t off=(uint32_t)((wm+mi*16+ar)*TROW + ac*2);
            ldsm4(ah[mi], sa+off); ldsm4(al[mi], sal+off);
        }
#pragma unroll
        for(int nj=0;nj<NI/2;nj++){
            uint32_t off=(uint32_t)((wn+nj*16+br)*TROW + bc*2);
            uint32_t r[4];
            ldsm4(r, sb+off);  bh[nj*2][0]=r[0]; bh[nj*2][1]=r[1]; bh[nj*2+1][0]=r[2]; bh[nj*2+1][1]=r[3];
            ldsm4(r, sbl+off); bl[nj*2][0]=r[0]; bl[nj*2][1]=r[1]; bl[nj*2+1][0]=r[2]; bl[nj*2+1][1]=r[3];
        }
#pragma unroll
        for(int mi=0;mi<4;mi++)
#pragma unroll
            for(int ni=0;ni<NI;ni++){
                float* d=acc[mi*NI+ni];
                mma16816(d, ah[mi], bh[ni]);
                mma16816(d, al[mi], bh[ni]);
                mma16816(d, ah[mi], bl[ni]);
            }
    }
}

// ---------- pipelined GEMM 128x128, 2-stage cp.async ----------
// stage layout: A=0, AL=18432, B=36864, BL=55296; stage stride 73728
#define GST 73728
#define GTOT2 (2*GST)
__global__ __launch_bounds__(256)
void gemm_bf3(const bf16* __restrict__ Ah, const bf16* __restrict__ Al, int lda,
              const bf16* __restrict__ Bh, const bf16* __restrict__ Bl, int K,
              const float* __restrict__ bias, int epi,
              float* __restrict__ of, bf16* __restrict__ oh, bf16* __restrict__ ol,
              int ldc, float alpha, const float* __restrict__ pe){
    extern __shared__ char smem[];
    uint32_t sb0=smem_u32(smem);
    int tid=threadIdx.x, wid=tid>>5, lane=tid&31;
    int row0=blockIdx.y*128, col0=blockIdx.x*128;
    int wm=(wid>>2)*64, wn=(wid&3)*32;
    float acc[16][4];
#pragma unroll
    for(int i=0;i<16;i++){ acc[i][0]=0;acc[i][1]=0;acc[i][2]=0;acc[i][3]=0; }
    int NC=K/64;
    {
        uint32_t s=sb0;
        load_cp(s,       Ah,row0,0,lda,128);
        load_cp(s+18432, Al,row0,0,lda,128);
        load_cp(s+36864, Bh,col0,0,K,128);
        load_cp(s+55296, Bl,col0,0,K,128);
        CP_COMMIT();
    }
    for(int kc=0;kc<NC;kc++){
        if(kc+1<NC){
            uint32_t s=sb0+((kc+1)&1)*GST;
            int k0=(kc+1)*64;
            load_cp(s,       Ah,row0,k0,lda,128);
            load_cp(s+18432, Al,row0,k0,lda,128);
            load_cp(s+36864, Bh,col0,k0,K,128);
            load_cp(s+55296, Bl,col0,k0,K,128);
            CP_COMMIT();
            CP_WAIT1();
        } else CP_WAIT0();
        __syncthreads();
        uint32_t s=sb0+(kc&1)*GST;
        mma_chunk<4>(s,s+18432,s+36864,s+55296,acc,lane,wm,wn);
        __syncthreads();
    }
    int gid=lane>>2, tig=lane&3;
#pragma unroll
    for(int mi=0;mi<4;mi++)
#pragma unroll
    for(int ni=0;ni<4;ni++){
        float* d=acc[mi*4+ni];
#pragma unroll
        for(int hf=0;hf<2;hf++){
            int r=row0+wm+mi*16+gid+hf*8;
            int c=col0+wn+ni*8+tig*2;
            float v0=d[hf*2]+__ldg(&bias[c]), v1=d[hf*2+1]+__ldg(&bias[c+1]);
            if(epi==1){ v0=fmaxf(v0,0.f); v1=fmaxf(v1,0.f); }
            if(epi==4){
                const float* per=pe+(size_t)(r&(SEQ-1))*DMODEL+c;
                v0=v0*alpha+per[0]; v1=v1*alpha+per[1];
            }
            if(epi==3||epi==4) *(float2*)(of+(size_t)r*ldc+c)=make_float2(v0,v1);
            if(epi==0||epi==1||epi==4){
                bf16 h0,l0,h1,l1; split2(v0,h0,l0); split2(v1,h1,l1);
                __nv_bfloat162 H{h0,h1}, L{l0,l1};
                *(__nv_bfloat162*)(oh+(size_t)r*ldc+c)=H;
                *(__nv_bfloat162*)(ol+(size_t)r*ldc+c)=L;
            }
            if(epi==2){
                int b=r>>9, s=r&(SEQ-1);
#pragma unroll
                for(int u=0;u<2;u++){
                    int n=c+u; float v=u?v1:v0;
                    size_t off=((size_t)(b*NHEAD+(n>>6))*DHEAD+(n&63))*SEQ+s;
                    bf16 hh,ll; split2(v,hh,ll); oh[off]=hh; ol[off]=ll;
                }
            }
        }
    }
}

// ---------- QK^T -> f32 scores. single K-chunk (DHEAD=64). grid(4,4,BH) ----------
__global__ __launch_bounds__(256)
void qk_kernel(const bf16* __restrict__ qh, const bf16* __restrict__ ql,
               const bf16* __restrict__ kh, const bf16* __restrict__ kl,
               float* __restrict__ sc, float scale){
    extern __shared__ char smem[];
    uint32_t sb0=smem_u32(smem);
    int tid=threadIdx.x, wid=tid>>5, lane=tid&31;
    int z=blockIdx.z, b=z>>3, h=z&7;
    int row0=blockIdx.y*128, col0=blockIdx.x*128, k0=h*DHEAD;
    int wm=(wid>>2)*64, wn=(wid&3)*32;
    float acc[16][4];
#pragma unroll
    for(int i=0;i<16;i++){ acc[i][0]=0;acc[i][1]=0;acc[i][2]=0;acc[i][3]=0; }
    load_cp(sb0,       qh,b*SEQ+row0,k0,DMODEL,128);
    load_cp(sb0+18432, ql,b*SEQ+row0,k0,DMODEL,128);
    load_cp(sb0+36864, kh,b*SEQ+col0,k0,DMODEL,128);
    load_cp(sb0+55296, kl,b*SEQ+col0,k0,DMODEL,128);
    CP_COMMIT(); CP_WAIT0();
    __syncthreads();
    mma_chunk<4>(sb0,sb0+18432,sb0+36864,sb0+55296,acc,lane,wm,wn);
    int gid=lane>>2, tig=lane&3;
    float* eb=sc+(size_t)z*SEQ*SEQ;
#pragma unroll
    for(int mi=0;mi<4;mi++)
#pragma unroll
    for(int ni=0;ni<4;ni++){
        float* d=acc[mi*4+ni];
#pragma unroll
        for(int hf=0;hf<2;hf++){
            int r=row0+wm+mi*16+gid+hf*8, c=col0+wn+ni*8+tig*2;
            *(float2*)(eb+(size_t)r*SEQ+c)=make_float2(d[hf*2]*scale,d[hf*2+1]*scale);
        }
    }
}

// ---------- softmax -> unnormalized exp hi/lo + 1/sum ----------
__global__ __launch_bounds__(128)
void softmax_kernel(const float* __restrict__ sc, bf16* __restrict__ ph, bf16* __restrict__ pl,
                    float* __restrict__ sumr){
    __shared__ float red[128];
    int row=blockIdx.x, t=threadIdx.x;
    const float4* p=(const float4*)(sc+(size_t)row*SEQ);
    float4 v=p[t];
    float m=fmaxf(fmaxf(v.x,v.y),fmaxf(v.z,v.w));
    red[t]=m; __syncthreads();
    for(int s=64;s>0;s>>=1){ if(t<s) red[t]=fmaxf(red[t],red[t+s]); __syncthreads(); }
    m=red[0]; __syncthreads();
    float e0=__expf(v.x-m), e1=__expf(v.y-m), e2=__expf(v.z-m), e3=__expf(v.w-m);
    red[t]=e0+e1+e2+e3; __syncthreads();
    for(int s=64;s>0;s>>=1){ if(t<s) red[t]+=red[t+s]; __syncthreads(); }
    if(t==0) sumr[row]=1.0f/red[0];
    size_t off=(size_t)row*SEQ+t*4;
    bf16 h0,l0,h1,l1,h2,l2,h3,l3;
    split2(e0,h0,l0); split2(e1,h1,l1); split2(e2,h2,l2); split2(e3,h3,l3);
    __nv_bfloat162 H0{h0,h1},H1{h2,h3},L0{l0,l1},L1{l2,l3};
    *(__nv_bfloat162*)(ph+off)=H0; *(__nv_bfloat162*)(ph+off+2)=H1;
    *(__nv_bfloat162*)(pl+off)=L0; *(__nv_bfloat162*)(pl+off+2)=L1;
}

// ---------- attn @ V, pipelined. grid(4,BH). stage: A=0,AL=18432,B=36864,BL=46080 ----------
#define AST 55296
#define ATOT2 (2*AST)
__global__ __launch_bounds__(256)
void av_bf3(const bf16* __restrict__ ph, const bf16* __restrict__ pl,
            const bf16* __restrict__ vth, const bf16* __restrict__ vtl,
            const float* __restrict__ sumr, bf16* __restrict__ ch, bf16* __restrict__ cl){
    extern __shared__ char smem[];
    uint32_t sb0=smem_u32(smem);
    int tid=threadIdx.x, wid=tid>>5, lane=tid&31;
    int z=blockIdx.y, b=z>>3, h=z&7;
    int row0=blockIdx.x*128;
    int wm=(wid>>2)*64, wn=(wid&3)*16;
    float acc[8][4];
#pragma unroll
    for(int i=0;i<8;i++){ acc[i][0]=0;acc[i][1]=0;acc[i][2]=0;acc[i][3]=0; }
    const bf16* pbh=ph+(size_t)z*SEQ*SEQ;
    const bf16* pbl=pl+(size_t)z*SEQ*SEQ;
    {
        uint32_t s=sb0;
        load_cp(s,       pbh,row0,0,SEQ,128);
        load_cp(s+18432, pbl,row0,0,SEQ,128);
        load_cp(s+36864, vth,z*DHEAD,0,SEQ,64);
        load_cp(s+46080, vtl,z*DHEAD,0,SEQ,64);
        CP_COMMIT();
    }
    for(int kc=0;kc<8;kc++){
        if(kc+1<8){
            uint32_t s=sb0+((kc+1)&1)*AST;
            int k0=(kc+1)*64;
            load_cp(s,       pbh,row0,k0,SEQ,128);
            load_cp(s+18432, pbl,row0,k0,SEQ,128);
            load_cp(s+36864, vth,z*DHEAD,k0,SEQ,64);
            load_cp(s+46080, vtl,z*DHEAD,k0,SEQ,64);
            CP_COMMIT();
            CP_WAIT1();
        } else CP_WAIT0();
        __syncthreads();
        uint32_t s=sb0+(kc&1)*AST;
        mma_chunk<2>(s,s+18432,s+36864,s+46080,acc,lane,wm,wn);
        __syncthreads();
    }
    int gid=lane>>2, tig=lane&3;
#pragma unroll
    for(int mi=0;mi<4;mi++)
#pragma unroll
    for(int ni=0;ni<2;ni++){
        float* d=acc[mi*2+ni];
#pragma unroll
        for(int hf=0;hf<2;hf++){
            int rl=row0+wm+mi*16+gid+hf*8;
            float inv=sumr[(size_t)z*SEQ+rl];
            int token=b*SEQ+rl, c=wn+ni*8+tig*2;
            float v0=d[hf*2]*inv, v1=d[hf*2+1]*inv;
            bf16 h0,l0,h1,l1; split2(v0,h0,l0); split2(v1,h1,l1);
            __nv_bfloat162 H{h0,h1}, L{l0,l1};
            size_t off=(size_t)token*DMODEL+h*DHEAD+c;
            *(__nv_bfloat162*)(ch+off)=H; *(__nv_bfloat162*)(cl+off)=L;
        }
    }
}

// ---------- residual + LN -> f32 + hi/lo ----------
__global__ __launch_bounds__(128)
void ln_kernel(const float* __restrict__ x, const float* __restrict__ res,
               const float* __restrict__ gs, const float* __restrict__ gb,
               float* __restrict__ out, bf16* __restrict__ oh, bf16* __restrict__ ol){
    __shared__ float red[128];
    int row=blockIdx.x, t=threadIdx.x;
    float4 a=*(const float4*)&x[(size_t)row*DMODEL+t*4];
    float4 r=*(const float4*)&res[(size_t)row*DMODEL+t*4];
    float y0=a.x+r.x, y1=a.y+r.y, y2=a.z+r.z, y3=a.w+r.w;
    red[t]=y0+y1+y2+y3; __syncthreads();
    for(int s=64;s>0;s>>=1){ if(t<s) red[t]+=red[t+s]; __syncthreads(); }
    float mu=red[0]*(1.0f/DMODEL); __syncthreads();
    float d0=y0-mu,d1=y1-mu,d2=y2-mu,d3=y3-mu;
    red[t]=d0*d0+d1*d1+d2*d2+d3*d3; __syncthreads();
    for(int s=64;s>0;s>>=1){ if(t<s) red[t]+=red[t+s]; __syncthreads(); }
    float k=rsqrtf(red[0]*(1.0f/DMODEL)+1e-5f);
    float4 sv=*(const float4*)&gs[t*4], bv=*(const float4*)&gb[t*4];
    float o0=d0*k*sv.x+bv.x, o1=d1*k*sv.y+bv.y, o2=d2*k*sv.z+bv.z, o3=d3*k*sv.w+bv.w;
    *(float4*)&out[(size_t)row*DMODEL+t*4]=make_float4(o0,o1,o2,o3);
    size_t off=(size_t)row*DMODEL+t*4;
    bf16 h0,l0,h1,l1,h2,l2,h3,l3;
    split2(o0,h0,l0); split2(o1,h1,l1); split2(o2,h2,l2); split2(o3,h3,l3);
    __nv_bfloat162 H0{h0,h1},H1{h2,h3},L0{l0,l1},L1{l2,l3};
    *(__nv_bfloat162*)(oh+off)=H0; *(__nv_bfloat162*)(oh+off+2)=H1;
    *(__nv_bfloat162*)(ol+off)=L0; *(__nv_bfloat162*)(ol+off+2)=L1;
}

// ---------- host ----------
#define GETP(sym,p,T) do{ void* _t; cudaGetSymbolAddress(&_t,sym); p=(T*)_t; }while(0)

extern "C" void kernel_launch(void* const* d_in, const int* in_sizes, int n_in,
                              void* d_out, int out_size){
    const float* source=(const float*)d_in[0];
    const float* fin_w1=(const float*)d_in[2];
    const float* fin_b1=(const float*)d_in[3];
    const float* fin_w2=(const float*)d_in[4];
    const float* fin_b2=(const float*)d_in[5];
    const float* wq=(const float*)d_in[6];  const float* bq=(const float*)d_in[7];
    const float* wk=(const float*)d_in[8];  const float* bk=(const float*)d_in[9];
    const float* wv=(const float*)d_in[10]; const float* bvv=(const float*)d_in[11];
    const float* wo=(const float*)d_in[12]; const float* bo=(const float*)d_in[13];
    const float* n1s=(const float*)d_in[14]; const float* n1b=(const float*)d_in[15];
    const float* ffw1=(const float*)d_in[16]; const float* ffb1=(const float*)d_in[17];
    const float* ffw2=(const float*)d_in[18]; const float* ffb2=(const float*)d_in[19];
    const float* n2s=(const float*)d_in[20]; const float* n2b=(const float*)d_in[21];
    float* out=(float*)d_out;

    float *ppe,*px,*ptmp,*psumr,*psc;
    GETP(g_pe,ppe,float); GETP(g_x,px,float); GETP(g_tmp,ptmp,float);
    GETP(g_sumr,psumr,float); GETP(g_sc,psc,float);
    bf16 *srch,*srcl,*xh,*xl,*qh,*ql,*kh,*kl,*vth,*vtl,*chh,*cll,*fhh,*fll,*phh,*pll;
    GETP(g_srch,srch,bf16); GETP(g_srcl,srcl,bf16);
    GETP(g_xh,xh,bf16); GETP(g_xl,xl,bf16);
    GETP(g_qh,qh,bf16); GETP(g_ql,ql,bf16);
    GETP(g_kh,kh,bf16); GETP(g_kl,kl,bf16);
    GETP(g_vth,vth,bf16); GETP(g_vtl,vtl,bf16);
    GETP(g_ch,chh,bf16); GETP(g_cl,cll,bf16);
    GETP(g_fh,fhh,bf16); GETP(g_fl,fll,bf16);
    GETP(g_ph,phh,bf16); GETP(g_pl,pll,bf16);
    bf16 *fw1h,*fw1l,*fw2h,*fw2l,*wqh,*wqlo,*wkh,*wklo,*wvh,*wvlo,*woh,*wolo,*f1h,*f1l,*f2h,*f2l;
    GETP(g_fw1h,fw1h,bf16); GETP(g_fw1l,fw1l,bf16);
    GETP(g_fw2h,fw2h,bf16); GETP(g_fw2l,fw2l,bf16);
    GETP(g_wqh,wqh,bf16); GETP(g_wqlo,wqlo,bf16);
    GETP(g_wkh,wkh,bf16); GETP(g_wklo,wklo,bf16);
    GETP(g_wvh,wvh,bf16); GETP(g_wvlo,wvlo,bf16);
    GETP(g_woh,woh,bf16); GETP(g_wolo,wolo,bf16);
    GETP(g_f1h,f1h,bf16); GETP(g_f1l,f1l,bf16);
    GETP(g_f2h,f2h,bf16); GETP(g_f2l,f2l,bf16);

    cudaFuncSetAttribute(gemm_bf3,  cudaFuncAttributeMaxDynamicSharedMemorySize, GTOT2);
    cudaFuncSetAttribute(qk_kernel, cudaFuncAttributeMaxDynamicSharedMemorySize, GST);
    cudaFuncSetAttribute(av_bf3,    cudaFuncAttributeMaxDynamicSharedMemorySize, ATOT2);

    const float sqrtd=22.627416998f, scale=0.044194173824f;

    tsplit_all<<<TSPLIT_BLOCKS, dim3(32,8)>>>(fin_w1,fin_w2,wq,wk,wv,wo,ffw1,ffw2,
        fw1h,fw1l,fw2h,fw2l,wqh,wqlo,wkh,wklo,wvh,wvlo,woh,wolo,f1h,f1l,f2h,f2l);
    prep_misc<<<SEQ + (MTOK*DIN+255)/256, 256>>>(ppe, source, srch, srcl);

    gemm_bf3<<<dim3(16,32),256,GTOT2>>>(srch,srcl,DIN,fw1h,fw1l,DIN,fin_b1,1,nullptr,fhh,fll,DFF,0.f,nullptr);
    gemm_bf3<<<dim3(4,32),256,GTOT2>>>(fhh,fll,DFF,fw2h,fw2l,DFF,fin_b2,4,px,xh,xl,DMODEL,sqrtd,ppe);

    for(int l=0;l<NLAYER;l++){
        size_t w5=(size_t)l*DMODEL*DMODEL;
        size_t wf1=(size_t)l*DFF*DMODEL, wf2=(size_t)l*DMODEL*DFF;

        gemm_bf3<<<dim3(4,32),256,GTOT2>>>(xh,xl,DMODEL,wqh+w5,wqlo+w5,DMODEL,bq+l*DMODEL,0,nullptr,qh,ql,DMODEL,0.f,nullptr);
        gemm_bf3<<<dim3(4,32),256,GTOT2>>>(xh,xl,DMODEL,wkh+w5,wklo+w5,DMODEL,bk+l*DMODEL,0,nullptr,kh,kl,DMODEL,0.f,nullptr);
        gemm_bf3<<<dim3(4,32),256,GTOT2>>>(xh,xl,DMODEL,wvh+w5,wvlo+w5,DMODEL,bvv+l*DMODEL,2,nullptr,vth,vtl,DMODEL,0.f,nullptr);

        qk_kernel<<<dim3(4,4,BH),256,GST>>>(qh,ql,kh,kl,psc,scale);
        softmax_kernel<<<BH*SEQ,128>>>(psc,phh,pll,psumr);
        av_bf3<<<dim3(4,BH),256,ATOT2>>>(phh,pll,vth,vtl,psumr,chh,cll);

        gemm_bf3<<<dim3(4,32),256,GTOT2>>>(chh,cll,DMODEL,woh+w5,wolo+w5,DMODEL,bo+l*DMODEL,3,ptmp,nullptr,nullptr,DMODEL,0.f,nullptr);
        ln_kernel<<<MTOK,128>>>(px,ptmp,n1s+l*DMODEL,n1b+l*DMODEL,px,xh,xl);

        gemm_bf3<<<dim3(16,32),256,GTOT2>>>(xh,xl,DMODEL,f1h+wf1,f1l+wf1,DMODEL,ffb1+l*DFF,1,nullptr,fhh,fll,DFF,0.f,nullptr);
        gemm_bf3<<<dim3(4,32),256,GTOT2>>>(fhh,fll,DFF,f2h+wf2,f2l+wf2,DFF,ffb2+l*DMODEL,3,ptmp,nullptr,nullptr,DMODEL,0.f,nullptr);

        float* lnout=(l==NLAYER-1)?out:px;
        ln_kernel<<<MTOK,128>>>(px,ptmp,n2s+l*DMODEL,n2b+l*DMODEL,lnout,xh,xl);
    }
}